// round 1
// baseline (speedup 1.0000x reference)
#include <cuda_runtime.h>
#include <cuda_bf16.h>
#include <math.h>

// Problem constants (fixed shapes from reference: z_e [16,2048,256], embedding [8192,256])
#define NROWS 32768
#define DIM   256
#define KCODE 8192
#define NZ    8388608   // NROWS*DIM

// Output layout (float32):
//   [0, NZ)        z_q_st
//   [NZ, 2NZ)      z_q
//   [2NZ, 2NZ+N)   indices (as float)
//   [2NZ+N, +2)    stats: perplexity, dead_ratio
#define OFF_ZQ   8388608
#define OFF_IDX  16777216
#define OFF_ST   16809984

// Scratch (device globals; no allocations allowed)
__device__ float g_en2[KCODE];
__device__ int   g_best[NROWS];
__device__ int   g_usage[KCODE];

// ---------------------------------------------------------------------------
// Kernel 0: zero usage histogram + precompute ||e_j||^2
// ---------------------------------------------------------------------------
__global__ void prep_kernel(const float* __restrict__ E) {
    int j = blockIdx.x * blockDim.x + threadIdx.x;
    if (j >= KCODE) return;
    g_usage[j] = 0;
    const float4* p = reinterpret_cast<const float4*>(E + (size_t)j * DIM);
    float s = 0.0f;
#pragma unroll
    for (int i = 0; i < DIM / 4; i++) {
        float4 v = p[i];
        s = fmaf(v.x, v.x, s);
        s = fmaf(v.y, v.y, s);
        s = fmaf(v.z, v.z, s);
        s = fmaf(v.w, v.w, s);
    }
    g_en2[j] = s;
}

// ---------------------------------------------------------------------------
// Kernel 1: fused distance GEMM + argmin.
// CTA: 64 rows, full-D A tile resident in smem (64KB), stream codes in 64x32
// chunks. 256 threads, 4x4 register accumulators per thread.
// d(row,code) = ||e||^2 - 2 * <x,e>   (row-constant ||x||^2 dropped)
// ---------------------------------------------------------------------------
#define BM 64
#define BN 64
#define BK 32
#define SMEM_BYTES ((DIM * BM + BK * BM) * 4)   // 64KB A + 8KB B = 73728

__global__ __launch_bounds__(256) void vq_kernel(const float* __restrict__ A,
                                                 const float* __restrict__ E) {
    extern __shared__ float smem[];
    float* As = smem;              // [DIM][BM]  As[k*BM + r]
    float* Bs = smem + DIM * BM;   // [BK][BM]   Bs[kk*BM + r]

    const int tid = threadIdx.x;
    const int tx = tid & 15;       // code sub-block 0..15
    const int ty = tid >> 4;       // row  sub-block 0..15
    const int row0 = blockIdx.x * BM;

    // --- Load full A tile (64 rows x 256 cols), transposed into smem ---
    // 4096 float4 total, 16 per thread. Mapping keeps STS conflict-free
    // (consecutive threads -> consecutive rows at same column group).
    for (int l = tid; l < BM * (DIM / 4); l += 256) {
        int r  = l & (BM - 1);
        int c4 = (l >> 6) << 2;                 // 0,4,...,252
        float4 v = *reinterpret_cast<const float4*>(A + (size_t)(row0 + r) * DIM + c4);
        As[(c4 + 0) * BM + r] = v.x;
        As[(c4 + 1) * BM + r] = v.y;
        As[(c4 + 2) * BM + r] = v.z;
        As[(c4 + 3) * BM + r] = v.w;
    }

    float bestv[4];
    int   besti[4];
#pragma unroll
    for (int i = 0; i < 4; i++) { bestv[i] = 3.4e38f; besti[i] = 0; }

    for (int c0 = 0; c0 < KCODE; c0 += BN) {
        float acc[4][4];
#pragma unroll
        for (int i = 0; i < 4; i++)
#pragma unroll
            for (int j = 0; j < 4; j++) acc[i][j] = 0.0f;

        for (int k0 = 0; k0 < DIM; k0 += BK) {
            __syncthreads();   // previous Bs consumers done (also fences As on first pass)
            // Load B chunk: 64 codes x 32 cols = 512 float4, 2 per thread.
#pragma unroll
            for (int l = tid; l < BN * (BK / 4); l += 256) {
                int r  = l & (BN - 1);
                int c4 = (l >> 6) << 2;         // 0,4,...,28
                float4 w = *reinterpret_cast<const float4*>(
                    E + (size_t)(c0 + r) * DIM + k0 + c4);
                Bs[(c4 + 0) * BM + r] = w.x;
                Bs[(c4 + 1) * BM + r] = w.y;
                Bs[(c4 + 2) * BM + r] = w.z;
                Bs[(c4 + 3) * BM + r] = w.w;
            }
            __syncthreads();

#pragma unroll
            for (int kk = 0; kk < BK; kk++) {
                float4 a = *reinterpret_cast<const float4*>(&As[(k0 + kk) * BM + ty * 4]);
                float4 b = *reinterpret_cast<const float4*>(&Bs[kk * BM + tx * 4]);
                acc[0][0] = fmaf(a.x, b.x, acc[0][0]);
                acc[0][1] = fmaf(a.x, b.y, acc[0][1]);
                acc[0][2] = fmaf(a.x, b.z, acc[0][2]);
                acc[0][3] = fmaf(a.x, b.w, acc[0][3]);
                acc[1][0] = fmaf(a.y, b.x, acc[1][0]);
                acc[1][1] = fmaf(a.y, b.y, acc[1][1]);
                acc[1][2] = fmaf(a.y, b.z, acc[1][2]);
                acc[1][3] = fmaf(a.y, b.w, acc[1][3]);
                acc[2][0] = fmaf(a.z, b.x, acc[2][0]);
                acc[2][1] = fmaf(a.z, b.y, acc[2][1]);
                acc[2][2] = fmaf(a.z, b.z, acc[2][2]);
                acc[2][3] = fmaf(a.z, b.w, acc[2][3]);
                acc[3][0] = fmaf(a.w, b.x, acc[3][0]);
                acc[3][1] = fmaf(a.w, b.y, acc[3][1]);
                acc[3][2] = fmaf(a.w, b.z, acc[3][2]);
                acc[3][3] = fmaf(a.w, b.w, acc[3][3]);
            }
        }

        // Argmin update. Codes ascend within thread across c0, so strict '<'
        // keeps the first (lowest-index) occurrence of the min.
#pragma unroll
        for (int j = 0; j < 4; j++) {
            int code = c0 + tx * 4 + j;
            float en = g_en2[code];
#pragma unroll
            for (int i = 0; i < 4; i++) {
                float d = fmaf(-2.0f, acc[i][j], en);
                if (d < bestv[i]) { bestv[i] = d; besti[i] = code; }
            }
        }
    }

    // --- Cross-thread argmin reduction (reuse Bs region: 2048 floats) ---
    __syncthreads();
    float* redv = Bs;                              // [BM][16]
    int*   redi = reinterpret_cast<int*>(Bs + BM * 16);
#pragma unroll
    for (int i = 0; i < 4; i++) {
        redv[(ty * 4 + i) * 16 + tx] = bestv[i];
        redi[(ty * 4 + i) * 16 + tx] = besti[i];
    }
    __syncthreads();
    if (tid < BM) {
        float bv = redv[tid * 16];
        int   bi = redi[tid * 16];
#pragma unroll
        for (int t = 1; t < 16; t++) {
            float v = redv[tid * 16 + t];
            int   ii = redi[tid * 16 + t];
            if (v < bv || (v == bv && ii < bi)) { bv = v; bi = ii; }
        }
        g_best[row0 + tid] = bi;
    }
}

// ---------------------------------------------------------------------------
// Kernel 2: gather z_q, emit z_q_st = z_e + (z_q - z_e) exactly as reference
// rounds it, write indices as float, accumulate usage histogram.
// ---------------------------------------------------------------------------
__global__ void gather_kernel(const float* __restrict__ Z,
                              const float* __restrict__ E,
                              float* __restrict__ out) {
    int row = blockIdx.x;
    int t = threadIdx.x;
    int idx = g_best[row];
    size_t o = (size_t)row * DIM + t;
    float e  = E[(size_t)idx * DIM + t];
    float ze = Z[o];
    out[o] = ze + (e - ze);      // z_q_st: matches fp32 rounding of reference
    out[OFF_ZQ + o] = e;         // z_q
    if (t == 0) {
        out[OFF_IDX + row] = (float)idx;
        atomicAdd(&g_usage[idx], 1);
    }
}

// ---------------------------------------------------------------------------
// Kernel 3: perplexity + dead ratio (single CTA)
// ---------------------------------------------------------------------------
__global__ void stats_kernel(float* __restrict__ out) {
    __shared__ float se[256];
    __shared__ int   sd[256];
    int t = threadIdx.x;
    float ent = 0.0f;
    int dead = 0;
    for (int j = t; j < KCODE; j += 256) {
        int u = g_usage[j];
        if (u == 0) {
            dead++;
        } else {
            float p = (float)u * (1.0f / (float)NROWS);
            ent -= p * logf(p);
        }
    }
    se[t] = ent;
    sd[t] = dead;
    __syncthreads();
    for (int s = 128; s > 0; s >>= 1) {
        if (t < s) { se[t] += se[t + s]; sd[t] += sd[t + s]; }
        __syncthreads();
    }
    if (t == 0) {
        out[OFF_ST + 0] = expf(se[0]);                       // perplexity
        out[OFF_ST + 1] = (float)sd[0] / (float)KCODE;       // dead_ratio
    }
}

// ---------------------------------------------------------------------------
extern "C" void kernel_launch(void* const* d_in, const int* in_sizes, int n_in,
                              void* d_out, int out_size) {
    const float* z_e = (const float*)d_in[0];   // [16,2048,256] fp32
    const float* emb = (const float*)d_in[1];   // [8192,256]    fp32
    float* out = (float*)d_out;

    cudaFuncSetAttribute(vq_kernel, cudaFuncAttributeMaxDynamicSharedMemorySize,
                         SMEM_BYTES);

    prep_kernel<<<KCODE / 256, 256>>>(emb);
    vq_kernel<<<NROWS / BM, 256, SMEM_BYTES>>>(z_e, emb);
    gather_kernel<<<NROWS, 256>>>(z_e, emb, out);
    stats_kernel<<<1, 256>>>(out);
}

// round 2
// speedup vs baseline: 1.1009x; 1.1009x over previous
#include <cuda_runtime.h>
#include <cuda_bf16.h>
#include <math.h>

// Shapes: z_e [16,2048,256] fp32, embedding [8192,256] fp32
#define NROWS 32768
#define DIM   256
#define KCODE 8192
#define NZ    8388608

// Output layout (float32):
//   [0, NZ) z_q_st | [NZ,2NZ) z_q | [2NZ,2NZ+N) indices | +2 stats
#define OFF_ZQ   8388608
#define OFF_IDX  16777216
#define OFF_ST   16809984

__device__ float g_en2[KCODE];
__device__ int   g_best[NROWS];
__device__ int   g_usage[KCODE];

// ---------------------------------------------------------------------------
// Kernel 0: zero usage + ||e_j||^2
// ---------------------------------------------------------------------------
__global__ void prep_kernel(const float* __restrict__ E) {
    int j = blockIdx.x * blockDim.x + threadIdx.x;
    if (j >= KCODE) return;
    g_usage[j] = 0;
    const float4* p = reinterpret_cast<const float4*>(E + (size_t)j * DIM);
    float s = 0.0f;
#pragma unroll
    for (int i = 0; i < DIM / 4; i++) {
        float4 v = p[i];
        s = fmaf(v.x, v.x, s);
        s = fmaf(v.y, v.y, s);
        s = fmaf(v.z, v.z, s);
        s = fmaf(v.w, v.w, s);
    }
    g_en2[j] = s;
}

// ---------------------------------------------------------------------------
// Kernel 1: fused distance SGEMM + argmin.
// 128x128x16 tiles, 8x8 per-thread register blocking (1.0 B LDS per FMA),
// double-buffered smem, GMEM prefetch overlapped with compute.
// d(row,code) = ||e||^2 - 2*<x,e> (row constant ||x||^2 dropped).
// ---------------------------------------------------------------------------
#define BM 128
#define BN 128
#define BK 16
#define NSTEP  (DIM / BK)      // 16 k-steps per code chunk
#define NCHUNK (KCODE / BN)    // 64 code chunks
#define TOTSTEP (NSTEP * NCHUNK)

__global__ __launch_bounds__(256, 2) void vq_kernel(const float* __restrict__ A,
                                                    const float* __restrict__ E) {
    __shared__ float As[2][BK][BM];
    __shared__ float Bs[2][BK][BN];
    __shared__ float esm[2][BN];
    __shared__ float bsv[8][256];
    __shared__ int   bsi[8][256];

    const int tid = threadIdx.x;
    const int tx = tid & 15;            // col group 0..15 (8 codes each)
    const int ty = tid >> 4;            // row group 0..15 (8 rows each)
    const int row0 = blockIdx.x * BM;
    const int lr = tid & 127;           // ldg row / code within tile
    const int lc = tid >> 7;            // ldg col-group 0/1 (second at +2)

    const float* Abase = A + (size_t)(row0 + lr) * DIM;

#pragma unroll
    for (int i = 0; i < 8; i++) { bsv[i][tid] = 3.4e38f; bsi[i][tid] = 0; }

    float acc[8][8];
#pragma unroll
    for (int i = 0; i < 8; i++)
#pragma unroll
        for (int j = 0; j < 8; j++) acc[i][j] = 0.0f;

    // Prologue: stage step 0 (chunk 0, k0 = 0) into registers.
    float4 ra0 = *reinterpret_cast<const float4*>(Abase + lc * 4);
    float4 ra1 = *reinterpret_cast<const float4*>(Abase + (lc + 2) * 4);
    const float* Eb0 = E + (size_t)lr * DIM;
    float4 rb0 = *reinterpret_cast<const float4*>(Eb0 + lc * 4);
    float4 rb1 = *reinterpret_cast<const float4*>(Eb0 + (lc + 2) * 4);
    float re = (tid < BN) ? g_en2[tid] : 0.0f;

    for (int s = 0; s < TOTSTEP; s++) {
        const int kt = s & (NSTEP - 1);
        const int buf = s & 1;

        // Commit staged registers to smem buffer `buf`.
        As[buf][lc * 4 + 0][lr] = ra0.x;
        As[buf][lc * 4 + 1][lr] = ra0.y;
        As[buf][lc * 4 + 2][lr] = ra0.z;
        As[buf][lc * 4 + 3][lr] = ra0.w;
        As[buf][(lc + 2) * 4 + 0][lr] = ra1.x;
        As[buf][(lc + 2) * 4 + 1][lr] = ra1.y;
        As[buf][(lc + 2) * 4 + 2][lr] = ra1.z;
        As[buf][(lc + 2) * 4 + 3][lr] = ra1.w;
        Bs[buf][lc * 4 + 0][lr] = rb0.x;
        Bs[buf][lc * 4 + 1][lr] = rb0.y;
        Bs[buf][lc * 4 + 2][lr] = rb0.z;
        Bs[buf][lc * 4 + 3][lr] = rb0.w;
        Bs[buf][(lc + 2) * 4 + 0][lr] = rb1.x;
        Bs[buf][(lc + 2) * 4 + 1][lr] = rb1.y;
        Bs[buf][(lc + 2) * 4 + 2][lr] = rb1.z;
        Bs[buf][(lc + 2) * 4 + 3][lr] = rb1.w;
        if (kt == 0 && tid < BN) esm[(s >> 4) & 1][tid] = re;
        __syncthreads();

        // Prefetch next step from GMEM (overlaps with compute below).
        if (s + 1 < TOTSTEP) {
            const int s1 = s + 1;
            const int kt1 = s1 & (NSTEP - 1);
            const int c1 = s1 >> 4;               // chunk of next step
            const int k0 = kt1 * BK;
            ra0 = *reinterpret_cast<const float4*>(Abase + k0 + lc * 4);
            ra1 = *reinterpret_cast<const float4*>(Abase + k0 + (lc + 2) * 4);
            const float* Eb = E + (size_t)(c1 * BN + lr) * DIM + k0;
            rb0 = *reinterpret_cast<const float4*>(Eb + lc * 4);
            rb1 = *reinterpret_cast<const float4*>(Eb + (lc + 2) * 4);
            if (kt1 == 0 && tid < BN) re = g_en2[c1 * BN + tid];
        }

        // Compute: 16 kk x 64 FMA.
        for (int kk = 0; kk < BK; kk++) {
            float4 a0 = *reinterpret_cast<const float4*>(&As[buf][kk][ty * 8]);
            float4 a1 = *reinterpret_cast<const float4*>(&As[buf][kk][ty * 8 + 4]);
            float4 b0 = *reinterpret_cast<const float4*>(&Bs[buf][kk][tx * 8]);
            float4 b1 = *reinterpret_cast<const float4*>(&Bs[buf][kk][tx * 8 + 4]);
            float av[8] = {a0.x, a0.y, a0.z, a0.w, a1.x, a1.y, a1.z, a1.w};
            float bv[8] = {b0.x, b0.y, b0.z, b0.w, b1.x, b1.y, b1.z, b1.w};
#pragma unroll
            for (int i = 0; i < 8; i++)
#pragma unroll
                for (int j = 0; j < 8; j++)
                    acc[i][j] = fmaf(av[i], bv[j], acc[i][j]);
        }

        // Chunk epilogue: fold 8x8 distances into per-thread bests.
        if (kt == NSTEP - 1) {
            const int c0 = (s >> 4) * BN;
            const int eb = (s >> 4) & 1;
            float bvv[8]; int bii[8];
#pragma unroll
            for (int i = 0; i < 8; i++) { bvv[i] = bsv[i][tid]; bii[i] = bsi[i][tid]; }
#pragma unroll
            for (int j = 0; j < 8; j++) {
                const float en = esm[eb][tx * 8 + j];
                const int code = c0 + tx * 8 + j;
#pragma unroll
                for (int i = 0; i < 8; i++) {
                    float d = fmaf(-2.0f, acc[i][j], en);
                    // codes ascend within thread -> '<' keeps first occurrence
                    if (d < bvv[i]) { bvv[i] = d; bii[i] = code; }
                    acc[i][j] = 0.0f;
                }
            }
#pragma unroll
            for (int i = 0; i < 8; i++) { bsv[i][tid] = bvv[i]; bsi[i][tid] = bii[i]; }
        }
    }

    // Cross-thread argmin per row (16 tx candidates), lexicographic tie-break.
    __syncthreads();
    if (tid < BM) {
        const int i = tid & 7;
        const int base = (tid >> 3) * 16;   // ty group for this row
        float bv = bsv[i][base];
        int   bi = bsi[i][base];
#pragma unroll
        for (int t = 1; t < 16; t++) {
            float v = bsv[i][base + t];
            int  ii = bsi[i][base + t];
            if (v < bv || (v == bv && ii < bi)) { bv = v; bi = ii; }
        }
        g_best[row0 + tid] = bi;
    }
}

// ---------------------------------------------------------------------------
// Kernel 2: gather z_q / z_q_st, indices-as-float, usage histogram.
// ---------------------------------------------------------------------------
__global__ void gather_kernel(const float* __restrict__ Z,
                              const float* __restrict__ E,
                              float* __restrict__ out) {
    int row = blockIdx.x;
    int t = threadIdx.x;
    int idx = g_best[row];
    size_t o = (size_t)row * DIM + t;
    float e  = E[(size_t)idx * DIM + t];
    float ze = Z[o];
    out[o] = ze + (e - ze);      // z_q_st, reference fp32 rounding
    out[OFF_ZQ + o] = e;         // z_q
    if (t == 0) {
        out[OFF_IDX + row] = (float)idx;
        atomicAdd(&g_usage[idx], 1);
    }
}

// ---------------------------------------------------------------------------
// Kernel 3: perplexity + dead ratio (single CTA)
// ---------------------------------------------------------------------------
__global__ void stats_kernel(float* __restrict__ out) {
    __shared__ float se[256];
    __shared__ int   sd[256];
    int t = threadIdx.x;
    float ent = 0.0f;
    int dead = 0;
    for (int j = t; j < KCODE; j += 256) {
        int u = g_usage[j];
        if (u == 0) {
            dead++;
        } else {
            float p = (float)u * (1.0f / (float)NROWS);
            ent -= p * logf(p);
        }
    }
    se[t] = ent;
    sd[t] = dead;
    __syncthreads();
    for (int s = 128; s > 0; s >>= 1) {
        if (t < s) { se[t] += se[t + s]; sd[t] += sd[t + s]; }
        __syncthreads();
    }
    if (t == 0) {
        out[OFF_ST + 0] = expf(se[0]);
        out[OFF_ST + 1] = (float)sd[0] / (float)KCODE;
    }
}

// ---------------------------------------------------------------------------
extern "C" void kernel_launch(void* const* d_in, const int* in_sizes, int n_in,
                              void* d_out, int out_size) {
    const float* z_e = (const float*)d_in[0];
    const float* emb = (const float*)d_in[1];
    float* out = (float*)d_out;

    prep_kernel<<<KCODE / 256, 256>>>(emb);
    vq_kernel<<<NROWS / BM, 256>>>(z_e, emb);
    gather_kernel<<<NROWS, 256>>>(z_e, emb, out);
    stats_kernel<<<1, 256>>>(out);
}

// round 4
// speedup vs baseline: 12.1198x; 11.0091x over previous
#include <cuda_runtime.h>
#include <cuda_bf16.h>
#include <math.h>
#include <stdint.h>

// Shapes: z_e [16,2048,256] fp32, embedding [8192,256] fp32
#define NROWS 32768
#define DIM   256
#define KCODE 8192
#define NZ    8388608
#define OFF_ZQ   8388608
#define OFF_IDX  16777216
#define OFF_ST   16809984

#define CAP   64
#define DELTA 0.30f     // > 2x worst-case bf16 screening error (0.13)

// ---------------- device scratch (static; no allocations) -------------------
__device__ float g_en2[KCODE];
__device__ int   g_best[NROWS];
__device__ int   g_usage[KCODE];
__device__ int   g_cnt[NROWS];
__device__ int   g_cand[NROWS * CAP];
__device__ __align__(16) __nv_bfloat16 g_Abf[NROWS * DIM];
__device__ __align__(16) __nv_bfloat16 g_Ebf[KCODE * DIM];

// ---------------- helpers ----------------------------------------------------
__device__ __forceinline__ uint32_t smem_u32(const void* p) {
    uint32_t a;
    asm("{ .reg .u64 t; cvta.to.shared.u64 t, %1; cvt.u32.u64 %0, t; }" : "=r"(a) : "l"(p));
    return a;
}
#define CP_ASYNC(dst, src) \
    asm volatile("cp.async.cg.shared.global [%0], [%1], 16;" :: "r"(dst), "l"(src) : "memory")
#define CP_COMMIT() asm volatile("cp.async.commit_group;" ::: "memory")
#define CP_WAIT1()  asm volatile("cp.async.wait_group 1;" ::: "memory")

#define LDSM_X4(r0, r1, r2, r3, addr) \
    asm volatile("ldmatrix.sync.aligned.m8n8.x4.shared.b16 {%0,%1,%2,%3}, [%4];" \
                 : "=r"(r0), "=r"(r1), "=r"(r2), "=r"(r3) : "r"(addr))

__device__ __forceinline__ void mma16816(float* d, const uint32_t* a, uint32_t b0, uint32_t b1) {
    asm volatile(
        "mma.sync.aligned.m16n8k16.row.col.f32.bf16.bf16.f32 "
        "{%0,%1,%2,%3}, {%4,%5,%6,%7}, {%8,%9}, {%0,%1,%2,%3};"
        : "+f"(d[0]), "+f"(d[1]), "+f"(d[2]), "+f"(d[3])
        : "r"(a[0]), "r"(a[1]), "r"(a[2]), "r"(a[3]), "r"(b0), "r"(b1));
}

// Swizzled byte offset inside a [rows x 256 bf16] tile: row r, 16B-chunk c (0..31).
// chunk XOR (r&7) keeps ldmatrix (8 rows, same chunk) conflict-free.
__device__ __forceinline__ uint32_t TOFF(int r, int c) {
    return ((uint32_t)r << 9) + ((uint32_t)(c ^ (r & 7)) << 4);
}

// ---------------- prep kernels ----------------------------------------------
__global__ void prep_a(const float* __restrict__ Z) {
    int i = blockIdx.x * blockDim.x + threadIdx.x;
    float4 v = reinterpret_cast<const float4*>(Z)[i];
    __nv_bfloat162 p0(__float2bfloat16(v.x), __float2bfloat16(v.y));
    __nv_bfloat162 p1(__float2bfloat16(v.z), __float2bfloat16(v.w));
    reinterpret_cast<__nv_bfloat162*>(g_Abf)[2 * i + 0] = p0;
    reinterpret_cast<__nv_bfloat162*>(g_Abf)[2 * i + 1] = p1;
}
__global__ void prep_econv(const float* __restrict__ E) {
    int i = blockIdx.x * blockDim.x + threadIdx.x;
    float4 v = reinterpret_cast<const float4*>(E)[i];
    __nv_bfloat162 p0(__float2bfloat16(v.x), __float2bfloat16(v.y));
    __nv_bfloat162 p1(__float2bfloat16(v.z), __float2bfloat16(v.w));
    reinterpret_cast<__nv_bfloat162*>(g_Ebf)[2 * i + 0] = p0;
    reinterpret_cast<__nv_bfloat162*>(g_Ebf)[2 * i + 1] = p1;
}
__global__ void prep_en2(const float* __restrict__ E) {
    int j = blockIdx.x * blockDim.x + threadIdx.x;
    if (j >= KCODE) return;
    g_usage[j] = 0;
    const float4* p = reinterpret_cast<const float4*>(E + (size_t)j * DIM);
    float s = 0.0f;
#pragma unroll
    for (int i = 0; i < DIM / 4; i++) {
        float4 v = p[i];
        s = fmaf(v.x, v.x, s); s = fmaf(v.y, v.y, s);
        s = fmaf(v.z, v.z, s); s = fmaf(v.w, v.w, s);
    }
    g_en2[j] = s;
}

// ---------------- screening GEMM (mma.sync bf16) -----------------------------
// CTA: 128 rows (A resident, 64KB swizzled). 64 chunks of 128 codes,
// double-buffered via cp.async. Warp grid 2m x 4n, warp tile 64x32.
#define NCH   64
#define SM_A      0
#define SM_B0     65536           // two 64KB buffers
#define SM_ESM    196608          // 2 x 128 floats (en2 per chunk)
#define SM_ROWRED 197632          // 128 x 4 floats
#define SM_BEST   199680          // 128 floats
#define SM_CNT    200192          // 128 ints
#define SM_TOTAL  200704

__global__ __launch_bounds__(256, 1) void vq_screen() {
    extern __shared__ __align__(1024) char smem[];
    const uint32_t sb = smem_u32(smem);
    const int tid = threadIdx.x, lane = tid & 31, wid = tid >> 5;
    const int wm = wid & 1, wn = wid >> 1;
    const int row0 = blockIdx.x * 128;

    float* bestrow = reinterpret_cast<float*>(smem + SM_BEST);
    float* rowred  = reinterpret_cast<float*>(smem + SM_ROWRED);
    int*   scnt    = reinterpret_cast<int*>(smem + SM_CNT);
    if (tid < 128) { bestrow[tid] = 3.4e38f; scnt[tid] = 0; }

    // Prologue: group0 = A + B0 + esm0 ; group1 = B1 + esm1
#pragma unroll
    for (int t = 0; t < 16; t++) {
        int u = tid + t * 256, r = u >> 5, c = u & 31;
        CP_ASYNC(sb + SM_A + TOFF(r, c), g_Abf + (size_t)(row0 + r) * DIM + c * 8);
    }
#pragma unroll
    for (int t = 0; t < 16; t++) {
        int u = tid + t * 256, r = u >> 5, c = u & 31;
        CP_ASYNC(sb + SM_B0 + TOFF(r, c), g_Ebf + (size_t)r * DIM + c * 8);
    }
    if (tid < 32) CP_ASYNC(sb + SM_ESM + tid * 16, g_en2 + tid * 4);
    CP_COMMIT();
#pragma unroll
    for (int t = 0; t < 16; t++) {
        int u = tid + t * 256, r = u >> 5, c = u & 31;
        CP_ASYNC(sb + SM_B0 + 65536 + TOFF(r, c), g_Ebf + (size_t)(128 + r) * DIM + c * 8);
    }
    if (tid < 32) CP_ASYNC(sb + SM_ESM + 512 + tid * 16, g_en2 + 128 + tid * 4);
    CP_COMMIT();
    CP_WAIT1();
    __syncthreads();

    // Per-thread constant address parts (tile-row & 7 == lane & 7 everywhere).
    const int s7 = lane & 7;
    const int cxA = lane >> 4;            // A: k-half select
    const int cxB = (lane >> 3) & 1;      // B: k-half select
    uint32_t rowA[4], rowB[2];
#pragma unroll
    for (int i = 0; i < 4; i++)
        rowA[i] = sb + SM_A + ((uint32_t)(wm * 64 + i * 16 + ((lane >> 3) & 1) * 8 + s7) << 9);
#pragma unroll
    for (int jj = 0; jj < 2; jj++)
        rowB[jj] = (uint32_t)(wn * 32 + jj * 16 + ((lane >> 4) & 1) * 8 + s7) << 9;

    float acc[4][4][4];
#pragma unroll
    for (int i = 0; i < 4; i++)
#pragma unroll
        for (int j = 0; j < 4; j++)
#pragma unroll
            for (int r = 0; r < 4; r++) acc[i][j][r] = 0.0f;

    for (int ch = 0; ch < NCH; ch++) {
        const int buf = ch & 1;
        const uint32_t bbase = sb + SM_B0 + (uint32_t)buf * 65536;

        // ---- compute: 16 k-steps ----
#pragma unroll
        for (int ks = 0; ks < 16; ks++) {
            const uint32_t offA = (uint32_t)(((2 * ks + cxA) ^ s7) << 4);
            const uint32_t offB = (uint32_t)(((2 * ks + cxB) ^ s7) << 4);
            uint32_t a[4][4], b[2][4];
#pragma unroll
            for (int i = 0; i < 4; i++)
                LDSM_X4(a[i][0], a[i][1], a[i][2], a[i][3], rowA[i] + offA);
#pragma unroll
            for (int jj = 0; jj < 2; jj++)
                LDSM_X4(b[jj][0], b[jj][1], b[jj][2], b[jj][3], bbase + rowB[jj] + offB);
#pragma unroll
            for (int i = 0; i < 4; i++) {
                mma16816(acc[i][0], a[i], b[0][0], b[0][1]);
                mma16816(acc[i][1], a[i], b[0][2], b[0][3]);
                mma16816(acc[i][2], a[i], b[1][0], b[1][1]);
                mma16816(acc[i][3], a[i], b[1][2], b[1][3]);
            }
        }

        // ---- epilogue: distances + per-row chunk min ----
        const float* esm = reinterpret_cast<const float*>(smem + SM_ESM + buf * 512);
        float rmin[4][2];
#pragma unroll
        for (int i = 0; i < 4; i++) {
            rmin[i][0] = 3.4e38f; rmin[i][1] = 3.4e38f;
#pragma unroll
            for (int j = 0; j < 4; j++) {
                const int colb = wn * 32 + j * 8 + (lane & 3) * 2;
                const float e0 = esm[colb], e1 = esm[colb + 1];
                float d0 = fmaf(-2.0f, acc[i][j][0], e0);
                float d1 = fmaf(-2.0f, acc[i][j][1], e1);
                float d2 = fmaf(-2.0f, acc[i][j][2], e0);
                float d3 = fmaf(-2.0f, acc[i][j][3], e1);
                acc[i][j][0] = d0; acc[i][j][1] = d1;
                acc[i][j][2] = d2; acc[i][j][3] = d3;
                rmin[i][0] = fminf(rmin[i][0], fminf(d0, d1));
                rmin[i][1] = fminf(rmin[i][1], fminf(d2, d3));
            }
            rmin[i][0] = fminf(rmin[i][0], __shfl_xor_sync(0xffffffffu, rmin[i][0], 1));
            rmin[i][0] = fminf(rmin[i][0], __shfl_xor_sync(0xffffffffu, rmin[i][0], 2));
            rmin[i][1] = fminf(rmin[i][1], __shfl_xor_sync(0xffffffffu, rmin[i][1], 1));
            rmin[i][1] = fminf(rmin[i][1], __shfl_xor_sync(0xffffffffu, rmin[i][1], 2));
        }
        if ((lane & 3) == 0) {
#pragma unroll
            for (int i = 0; i < 4; i++) {
                const int r = wm * 64 + i * 16 + (lane >> 2);
                rowred[r * 4 + wn] = rmin[i][0];
                rowred[(r + 8) * 4 + wn] = rmin[i][1];
            }
        }
        __syncthreads();     // compute + rowred done for all warps

        // prefetch chunk ch+2 into buf (safe: all reads of buf finished)
        if (ch + 2 < NCH) {
            const uint32_t dbase = sb + SM_B0 + (uint32_t)buf * 65536;
            const __nv_bfloat16* src = g_Ebf + (size_t)(ch + 2) * 128 * DIM;
#pragma unroll
            for (int t = 0; t < 16; t++) {
                int u = tid + t * 256, r = u >> 5, c = u & 31;
                CP_ASYNC(dbase + TOFF(r, c), src + (size_t)r * DIM + c * 8);
            }
            if (tid < 32)
                CP_ASYNC(sb + SM_ESM + buf * 512 + tid * 16, g_en2 + (ch + 2) * 128 + tid * 4);
        }
        CP_COMMIT();
        if (tid < 128) {
            float m = fminf(fminf(rowred[tid * 4], rowred[tid * 4 + 1]),
                            fminf(rowred[tid * 4 + 2], rowred[tid * 4 + 3]));
            bestrow[tid] = fminf(bestrow[tid], m);
        }
        __syncthreads();     // bestrow updated

        // ---- candidate scan (d < bestrow + DELTA) ----
#pragma unroll
        for (int i = 0; i < 4; i++) {
            const int rA = wm * 64 + i * 16 + (lane >> 2);
            const int rB = rA + 8;
            const float lA = bestrow[rA] + DELTA;
            const float lB = bestrow[rB] + DELTA;
#pragma unroll
            for (int j = 0; j < 4; j++) {
                const int code = ch * 128 + wn * 32 + j * 8 + (lane & 3) * 2;
                if (acc[i][j][0] < lA) {
                    int s = atomicAdd(&scnt[rA], 1);
                    if (s < CAP) g_cand[(size_t)(row0 + rA) * CAP + s] = code;
                }
                if (acc[i][j][1] < lA) {
                    int s = atomicAdd(&scnt[rA], 1);
                    if (s < CAP) g_cand[(size_t)(row0 + rA) * CAP + s] = code + 1;
                }
                if (acc[i][j][2] < lB) {
                    int s = atomicAdd(&scnt[rB], 1);
                    if (s < CAP) g_cand[(size_t)(row0 + rB) * CAP + s] = code;
                }
                if (acc[i][j][3] < lB) {
                    int s = atomicAdd(&scnt[rB], 1);
                    if (s < CAP) g_cand[(size_t)(row0 + rB) * CAP + s] = code + 1;
                }
                acc[i][j][0] = 0.0f; acc[i][j][1] = 0.0f;
                acc[i][j][2] = 0.0f; acc[i][j][3] = 0.0f;
            }
        }
        CP_WAIT1();          // chunk ch+1 resident
        __syncthreads();
    }

    if (tid < 128) g_cnt[row0 + tid] = scnt[tid];
}

// ---------------- exact rescore (fp32, first-occurrence argmin) --------------
__global__ void rescore(const float* __restrict__ Z, const float* __restrict__ E) {
    const int warp = (blockIdx.x * blockDim.x + threadIdx.x) >> 5;
    const int lane = threadIdx.x & 31;
    if (warp >= NROWS) return;
    const float4* zp = reinterpret_cast<const float4*>(Z + (size_t)warp * DIM);
    const float4 a0 = zp[lane * 2], a1 = zp[lane * 2 + 1];
    const int cnt = g_cnt[warp];
    const bool full = cnt > CAP;
    const int n = full ? KCODE : cnt;
    float bd = 3.4e38f; int bi = 0;
    for (int k = 0; k < n; k++) {
        const int code = full ? k : g_cand[(size_t)warp * CAP + k];
        const float4* e = reinterpret_cast<const float4*>(E + (size_t)code * DIM);
        const float4 e0 = e[lane * 2], e1 = e[lane * 2 + 1];
        float s = a0.x * e0.x;
        s = fmaf(a0.y, e0.y, s); s = fmaf(a0.z, e0.z, s); s = fmaf(a0.w, e0.w, s);
        s = fmaf(a1.x, e1.x, s); s = fmaf(a1.y, e1.y, s);
        s = fmaf(a1.z, e1.z, s); s = fmaf(a1.w, e1.w, s);
#pragma unroll
        for (int o = 16; o; o >>= 1) s += __shfl_xor_sync(0xffffffffu, s, o);
        float d = fmaf(-2.0f, s, g_en2[code]);
        if (d < bd || (d == bd && code < bi)) { bd = d; bi = code; }
    }
    if (lane == 0) g_best[warp] = bi;
}

// ---------------- gather + stats ---------------------------------------------
__global__ void gather_kernel(const float* __restrict__ Z,
                              const float* __restrict__ E,
                              float* __restrict__ out) {
    int row = blockIdx.x;
    int t = threadIdx.x;
    int idx = g_best[row];
    size_t o = (size_t)row * DIM + t;
    float e = E[(size_t)idx * DIM + t];
    float ze = Z[o];
    out[o] = ze + (e - ze);
    out[OFF_ZQ + o] = e;
    if (t == 0) {
        out[OFF_IDX + row] = (float)idx;
        atomicAdd(&g_usage[idx], 1);
    }
}

__global__ void stats_kernel(float* __restrict__ out) {
    __shared__ float se[1024];
    __shared__ int   sd[1024];
    int t = threadIdx.x;
    float ent = 0.0f; int dead = 0;
    for (int j = t; j < KCODE; j += 1024) {
        int u = g_usage[j];
        if (u == 0) dead++;
        else { float p = (float)u * (1.0f / (float)NROWS); ent -= p * logf(p); }
    }
    se[t] = ent; sd[t] = dead;
    __syncthreads();
    for (int s = 512; s > 0; s >>= 1) {
        if (t < s) { se[t] += se[t + s]; sd[t] += sd[t + s]; }
        __syncthreads();
    }
    if (t == 0) {
        out[OFF_ST + 0] = expf(se[0]);
        out[OFF_ST + 1] = (float)sd[0] / (float)KCODE;
    }
}

// ---------------------------------------------------------------------------
extern "C" void kernel_launch(void* const* d_in, const int* in_sizes, int n_in,
                              void* d_out, int out_size) {
    const float* z_e = (const float*)d_in[0];
    const float* emb = (const float*)d_in[1];
    float* out = (float*)d_out;

    cudaFuncSetAttribute(vq_screen, cudaFuncAttributeMaxDynamicSharedMemorySize, SM_TOTAL);

    prep_a<<<NZ / 1024, 256>>>(z_e);
    prep_econv<<<(KCODE * DIM) / 1024, 256>>>(emb);
    prep_en2<<<KCODE / 256, 256>>>(emb);
    vq_screen<<<NROWS / 128, 256, SM_TOTAL>>>();
    rescore<<<NROWS / 8, 256>>>(z_e, emb);
    gather_kernel<<<NROWS, 256>>>(z_e, emb, out);
    stats_kernel<<<1, 1024>>>(out);
}

// round 5
// speedup vs baseline: 13.8633x; 1.1439x over previous
#include <cuda_runtime.h>
#include <cuda_bf16.h>
#include <math.h>
#include <stdint.h>

// Shapes: z_e [16,2048,256] fp32, embedding [8192,256] fp32
#define NROWS 32768
#define DIM   256
#define KCODE 8192
#define NZ    8388608
#define OFF_ZQ   8388608
#define OFF_IDX  16777216
#define OFF_ST   16809984

#define CAP   64
#define DELTA 0.30f     // > 2x worst-case bf16 screening error (0.13)

// ---------------- device scratch (static; no allocations) -------------------
__device__ float g_en2[KCODE];
__device__ int   g_usage[KCODE];
__device__ int   g_cnt[NROWS];
__device__ int   g_cand[NROWS * CAP];
__device__ __align__(16) __nv_bfloat16 g_Abf[NROWS * DIM];
__device__ __align__(16) __nv_bfloat16 g_Ebf[KCODE * DIM];

// ---------------- helpers ----------------------------------------------------
__device__ __forceinline__ uint32_t smem_u32(const void* p) {
    uint32_t a;
    asm("{ .reg .u64 t; cvta.to.shared.u64 t, %1; cvt.u32.u64 %0, t; }" : "=r"(a) : "l"(p));
    return a;
}
#define CP_ASYNC(dst, src) \
    asm volatile("cp.async.cg.shared.global [%0], [%1], 16;" :: "r"(dst), "l"(src) : "memory")
#define CP_COMMIT() asm volatile("cp.async.commit_group;" ::: "memory")
#define CP_WAIT1()  asm volatile("cp.async.wait_group 1;" ::: "memory")

#define LDSM_X4(r0, r1, r2, r3, addr) \
    asm volatile("ldmatrix.sync.aligned.m8n8.x4.shared.b16 {%0,%1,%2,%3}, [%4];" \
                 : "=r"(r0), "=r"(r1), "=r"(r2), "=r"(r3) : "r"(addr))

__device__ __forceinline__ void mma16816(float* d, const uint32_t* a, uint32_t b0, uint32_t b1) {
    asm volatile(
        "mma.sync.aligned.m16n8k16.row.col.f32.bf16.bf16.f32 "
        "{%0,%1,%2,%3}, {%4,%5,%6,%7}, {%8,%9}, {%0,%1,%2,%3};"
        : "+f"(d[0]), "+f"(d[1]), "+f"(d[2]), "+f"(d[3])
        : "r"(a[0]), "r"(a[1]), "r"(a[2]), "r"(a[3]), "r"(b0), "r"(b1));
}

// Swizzled byte offset inside a [rows x 256 bf16] tile: row r, 16B-chunk c (0..31).
__device__ __forceinline__ uint32_t TOFF(int r, int c) {
    return ((uint32_t)r << 9) + ((uint32_t)(c ^ (r & 7)) << 4);
}

// ---------------- prep kernels ----------------------------------------------
__global__ void prep_a(const float* __restrict__ Z) {
    int i = blockIdx.x * blockDim.x + threadIdx.x;
    float4 v = reinterpret_cast<const float4*>(Z)[i];
    __nv_bfloat162 p0(__float2bfloat16(v.x), __float2bfloat16(v.y));
    __nv_bfloat162 p1(__float2bfloat16(v.z), __float2bfloat16(v.w));
    reinterpret_cast<__nv_bfloat162*>(g_Abf)[2 * i + 0] = p0;
    reinterpret_cast<__nv_bfloat162*>(g_Abf)[2 * i + 1] = p1;
}
__global__ void prep_econv(const float* __restrict__ E) {
    int i = blockIdx.x * blockDim.x + threadIdx.x;
    float4 v = reinterpret_cast<const float4*>(E)[i];
    __nv_bfloat162 p0(__float2bfloat16(v.x), __float2bfloat16(v.y));
    __nv_bfloat162 p1(__float2bfloat16(v.z), __float2bfloat16(v.w));
    reinterpret_cast<__nv_bfloat162*>(g_Ebf)[2 * i + 0] = p0;
    reinterpret_cast<__nv_bfloat162*>(g_Ebf)[2 * i + 1] = p1;
}
__global__ void prep_en2(const float* __restrict__ E) {
    int j = blockIdx.x * blockDim.x + threadIdx.x;
    if (j >= KCODE) return;
    g_usage[j] = 0;
    const float4* p = reinterpret_cast<const float4*>(E + (size_t)j * DIM);
    float s = 0.0f;
#pragma unroll
    for (int i = 0; i < DIM / 4; i++) {
        float4 v = p[i];
        s = fmaf(v.x, v.x, s); s = fmaf(v.y, v.y, s);
        s = fmaf(v.z, v.z, s); s = fmaf(v.w, v.w, s);
    }
    g_en2[j] = s;
}

// ---------------- screening GEMM (mma.sync bf16) -----------------------------
// CTA: 128 rows (A resident, 64KB swizzled), 512 threads, warp grid 4m x 4n,
// warp tile 32x32. 64 chunks of 128 codes, double-buffered via cp.async.
#define NCH   64
#define SM_A      0
#define SM_B0     65536           // two 64KB buffers
#define SM_ESM    196608          // 2 x 128 floats
#define SM_ROWRED 197632          // 128 x 4 floats
#define SM_BEST   199680          // 128 floats
#define SM_CNT    200192          // 128 ints
#define SM_TOTAL  200704

__global__ __launch_bounds__(512, 1) void vq_screen() {
    extern __shared__ __align__(1024) char smem[];
    const uint32_t sb = smem_u32(smem);
    const int tid = threadIdx.x, lane = tid & 31, wid = tid >> 5;
    const int wm = wid & 3, wn = wid >> 2;
    const int row0 = blockIdx.x * 128;

    float* bestrow = reinterpret_cast<float*>(smem + SM_BEST);
    float* rowred  = reinterpret_cast<float*>(smem + SM_ROWRED);
    int*   scnt    = reinterpret_cast<int*>(smem + SM_CNT);
    if (tid < 128) { bestrow[tid] = 3.4e38f; scnt[tid] = 0; }

    // Prologue: group0 = A + B0 + esm0 ; group1 = B1 + esm1
#pragma unroll
    for (int t = 0; t < 8; t++) {
        int u = tid + t * 512, r = u >> 5, c = u & 31;
        CP_ASYNC(sb + SM_A + TOFF(r, c), g_Abf + (size_t)(row0 + r) * DIM + c * 8);
    }
#pragma unroll
    for (int t = 0; t < 8; t++) {
        int u = tid + t * 512, r = u >> 5, c = u & 31;
        CP_ASYNC(sb + SM_B0 + TOFF(r, c), g_Ebf + (size_t)r * DIM + c * 8);
    }
    if (tid < 32) CP_ASYNC(sb + SM_ESM + tid * 16, g_en2 + tid * 4);
    CP_COMMIT();
#pragma unroll
    for (int t = 0; t < 8; t++) {
        int u = tid + t * 512, r = u >> 5, c = u & 31;
        CP_ASYNC(sb + SM_B0 + 65536 + TOFF(r, c), g_Ebf + (size_t)(128 + r) * DIM + c * 8);
    }
    if (tid < 32) CP_ASYNC(sb + SM_ESM + 512 + tid * 16, g_en2 + 128 + tid * 4);
    CP_COMMIT();
    CP_WAIT1();
    __syncthreads();

    const int s7 = lane & 7;
    const int cxA = lane >> 4;
    const int cxB = (lane >> 3) & 1;
    uint32_t rowA[2], rowB[2];
#pragma unroll
    for (int i = 0; i < 2; i++)
        rowA[i] = sb + SM_A + ((uint32_t)(wm * 32 + i * 16 + ((lane >> 3) & 1) * 8 + s7) << 9);
#pragma unroll
    for (int jj = 0; jj < 2; jj++)
        rowB[jj] = (uint32_t)(wn * 32 + jj * 16 + ((lane >> 4) & 1) * 8 + s7) << 9;

    float acc[2][4][4];
#pragma unroll
    for (int i = 0; i < 2; i++)
#pragma unroll
        for (int j = 0; j < 4; j++)
#pragma unroll
            for (int r = 0; r < 4; r++) acc[i][j][r] = 0.0f;

    for (int ch = 0; ch < NCH; ch++) {
        const int buf = ch & 1;
        const uint32_t bbase = sb + SM_B0 + (uint32_t)buf * 65536;

        // ---- compute: 16 k-steps ----
#pragma unroll
        for (int ks = 0; ks < 16; ks++) {
            const uint32_t offA = (uint32_t)(((2 * ks + cxA) ^ s7) << 4);
            const uint32_t offB = (uint32_t)(((2 * ks + cxB) ^ s7) << 4);
            uint32_t a[2][4], b[2][4];
#pragma unroll
            for (int i = 0; i < 2; i++)
                LDSM_X4(a[i][0], a[i][1], a[i][2], a[i][3], rowA[i] + offA);
#pragma unroll
            for (int jj = 0; jj < 2; jj++)
                LDSM_X4(b[jj][0], b[jj][1], b[jj][2], b[jj][3], bbase + rowB[jj] + offB);
#pragma unroll
            for (int i = 0; i < 2; i++) {
                mma16816(acc[i][0], a[i], b[0][0], b[0][1]);
                mma16816(acc[i][1], a[i], b[0][2], b[0][3]);
                mma16816(acc[i][2], a[i], b[1][0], b[1][1]);
                mma16816(acc[i][3], a[i], b[1][2], b[1][3]);
            }
        }

        // ---- epilogue: distances + per-row chunk min ----
        const float* esm = reinterpret_cast<const float*>(smem + SM_ESM + buf * 512);
        float rmin[2][2];
#pragma unroll
        for (int i = 0; i < 2; i++) {
            rmin[i][0] = 3.4e38f; rmin[i][1] = 3.4e38f;
#pragma unroll
            for (int j = 0; j < 4; j++) {
                const int colb = wn * 32 + j * 8 + (lane & 3) * 2;
                const float e0 = esm[colb], e1 = esm[colb + 1];
                float d0 = fmaf(-2.0f, acc[i][j][0], e0);
                float d1 = fmaf(-2.0f, acc[i][j][1], e1);
                float d2 = fmaf(-2.0f, acc[i][j][2], e0);
                float d3 = fmaf(-2.0f, acc[i][j][3], e1);
                acc[i][j][0] = d0; acc[i][j][1] = d1;
                acc[i][j][2] = d2; acc[i][j][3] = d3;
                rmin[i][0] = fminf(rmin[i][0], fminf(d0, d1));
                rmin[i][1] = fminf(rmin[i][1], fminf(d2, d3));
            }
            rmin[i][0] = fminf(rmin[i][0], __shfl_xor_sync(0xffffffffu, rmin[i][0], 1));
            rmin[i][0] = fminf(rmin[i][0], __shfl_xor_sync(0xffffffffu, rmin[i][0], 2));
            rmin[i][1] = fminf(rmin[i][1], __shfl_xor_sync(0xffffffffu, rmin[i][1], 1));
            rmin[i][1] = fminf(rmin[i][1], __shfl_xor_sync(0xffffffffu, rmin[i][1], 2));
        }
        if ((lane & 3) == 0) {
#pragma unroll
            for (int i = 0; i < 2; i++) {
                const int r = wm * 32 + i * 16 + (lane >> 2);
                rowred[r * 4 + wn] = rmin[i][0];
                rowred[(r + 8) * 4 + wn] = rmin[i][1];
            }
        }
        __syncthreads();

        // prefetch chunk ch+2 into buf
        if (ch + 2 < NCH) {
            const uint32_t dbase = sb + SM_B0 + (uint32_t)buf * 65536;
            const __nv_bfloat16* src = g_Ebf + (size_t)(ch + 2) * 128 * DIM;
#pragma unroll
            for (int t = 0; t < 8; t++) {
                int u = tid + t * 512, r = u >> 5, c = u & 31;
                CP_ASYNC(dbase + TOFF(r, c), src + (size_t)r * DIM + c * 8);
            }
            if (tid < 32)
                CP_ASYNC(sb + SM_ESM + buf * 512 + tid * 16, g_en2 + (ch + 2) * 128 + tid * 4);
        }
        CP_COMMIT();
        if (tid < 128) {
            float m = fminf(fminf(rowred[tid * 4], rowred[tid * 4 + 1]),
                            fminf(rowred[tid * 4 + 2], rowred[tid * 4 + 3]));
            bestrow[tid] = fminf(bestrow[tid], m);
        }
        __syncthreads();

        // ---- candidate scan (d < bestrow + DELTA) ----
#pragma unroll
        for (int i = 0; i < 2; i++) {
            const int rA = wm * 32 + i * 16 + (lane >> 2);
            const int rB = rA + 8;
            const float lA = bestrow[rA] + DELTA;
            const float lB = bestrow[rB] + DELTA;
#pragma unroll
            for (int j = 0; j < 4; j++) {
                const int code = ch * 128 + wn * 32 + j * 8 + (lane & 3) * 2;
                if (acc[i][j][0] < lA) {
                    int s = atomicAdd(&scnt[rA], 1);
                    if (s < CAP) g_cand[(size_t)(row0 + rA) * CAP + s] = code;
                }
                if (acc[i][j][1] < lA) {
                    int s = atomicAdd(&scnt[rA], 1);
                    if (s < CAP) g_cand[(size_t)(row0 + rA) * CAP + s] = code + 1;
                }
                if (acc[i][j][2] < lB) {
                    int s = atomicAdd(&scnt[rB], 1);
                    if (s < CAP) g_cand[(size_t)(row0 + rB) * CAP + s] = code;
                }
                if (acc[i][j][3] < lB) {
                    int s = atomicAdd(&scnt[rB], 1);
                    if (s < CAP) g_cand[(size_t)(row0 + rB) * CAP + s] = code + 1;
                }
                acc[i][j][0] = 0.0f; acc[i][j][1] = 0.0f;
                acc[i][j][2] = 0.0f; acc[i][j][3] = 0.0f;
            }
        }
        CP_WAIT1();
        __syncthreads();
    }

    if (tid < 128) g_cnt[row0 + tid] = scnt[tid];
}

// ---------------- exact rescore + gather (fused) ------------------------------
// One warp per row. Butterfly-sum gives every lane the full dot product, so
// all lanes agree on the argmin; the warp then gathers E[best] and writes
// z_q_st / z_q / index directly.
__global__ void rescore_gather(const float* __restrict__ Z,
                               const float* __restrict__ E,
                               float* __restrict__ out) {
    const int row = (blockIdx.x * blockDim.x + threadIdx.x) >> 5;
    const int lane = threadIdx.x & 31;
    if (row >= NROWS) return;
    const float4* zp = reinterpret_cast<const float4*>(Z + (size_t)row * DIM);
    const float4 a0 = zp[lane * 2], a1 = zp[lane * 2 + 1];
    const int cnt = g_cnt[row];
    const bool full = cnt > CAP;
    const int n = full ? KCODE : cnt;
    float bd = 3.4e38f; int bi = 0;
    for (int k = 0; k < n; k++) {
        const int code = full ? k : g_cand[(size_t)row * CAP + k];
        const float4* e = reinterpret_cast<const float4*>(E + (size_t)code * DIM);
        const float4 e0 = e[lane * 2], e1 = e[lane * 2 + 1];
        float s = a0.x * e0.x;
        s = fmaf(a0.y, e0.y, s); s = fmaf(a0.z, e0.z, s); s = fmaf(a0.w, e0.w, s);
        s = fmaf(a1.x, e1.x, s); s = fmaf(a1.y, e1.y, s);
        s = fmaf(a1.z, e1.z, s); s = fmaf(a1.w, e1.w, s);
#pragma unroll
        for (int o = 16; o; o >>= 1) s += __shfl_xor_sync(0xffffffffu, s, o);
        float d = fmaf(-2.0f, s, g_en2[code]);
        if (d < bd || (d == bd && code < bi)) { bd = d; bi = code; }
    }
    // every lane agrees on bi; gather + write outputs
    const float4* e = reinterpret_cast<const float4*>(E + (size_t)bi * DIM);
    const float4 e0 = e[lane * 2], e1 = e[lane * 2 + 1];
    const size_t o = (size_t)row * DIM + lane * 8;
    float4 st0, st1;
    st0.x = a0.x + (e0.x - a0.x); st0.y = a0.y + (e0.y - a0.y);
    st0.z = a0.z + (e0.z - a0.z); st0.w = a0.w + (e0.w - a0.w);
    st1.x = a1.x + (e1.x - a1.x); st1.y = a1.y + (e1.y - a1.y);
    st1.z = a1.z + (e1.z - a1.z); st1.w = a1.w + (e1.w - a1.w);
    reinterpret_cast<float4*>(out + o)[0] = st0;
    reinterpret_cast<float4*>(out + o)[1] = st1;
    reinterpret_cast<float4*>(out + OFF_ZQ + o)[0] = e0;
    reinterpret_cast<float4*>(out + OFF_ZQ + o)[1] = e1;
    if (lane == 0) {
        out[OFF_IDX + row] = (float)bi;
        atomicAdd(&g_usage[bi], 1);
    }
}

// ---------------- stats -------------------------------------------------------
__global__ void stats_kernel(float* __restrict__ out) {
    __shared__ float se[1024];
    __shared__ int   sd[1024];
    int t = threadIdx.x;
    float ent = 0.0f; int dead = 0;
    for (int j = t; j < KCODE; j += 1024) {
        int u = g_usage[j];
        if (u == 0) dead++;
        else { float p = (float)u * (1.0f / (float)NROWS); ent -= p * logf(p); }
    }
    se[t] = ent; sd[t] = dead;
    __syncthreads();
    for (int s = 512; s > 0; s >>= 1) {
        if (t < s) { se[t] += se[t + s]; sd[t] += sd[t + s]; }
        __syncthreads();
    }
    if (t == 0) {
        out[OFF_ST + 0] = expf(se[0]);
        out[OFF_ST + 1] = (float)sd[0] / (float)KCODE;
    }
}

// ---------------------------------------------------------------------------
extern "C" void kernel_launch(void* const* d_in, const int* in_sizes, int n_in,
                              void* d_out, int out_size) {
    const float* z_e = (const float*)d_in[0];
    const float* emb = (const float*)d_in[1];
    float* out = (float*)d_out;

    cudaFuncSetAttribute(vq_screen, cudaFuncAttributeMaxDynamicSharedMemorySize, SM_TOTAL);

    prep_a<<<NZ / 1024, 256>>>(z_e);
    prep_econv<<<(KCODE * DIM) / 1024, 256>>>(emb);
    prep_en2<<<KCODE / 256, 256>>>(emb);
    vq_screen<<<NROWS / 128, 512, SM_TOTAL>>>();
    rescore_gather<<<NROWS / 8, 256>>>(z_e, emb, out);
    stats_kernel<<<1, 1024>>>(out);
}

// round 9
// speedup vs baseline: 14.0774x; 1.0154x over previous
#include <cuda_runtime.h>
#include <cuda_bf16.h>
#include <math.h>
#include <stdint.h>

// Shapes: z_e [16,2048,256] fp32, embedding [8192,256] fp32
#define NROWS 32768
#define DIM   256
#define KCODE 8192
#define NZ    8388608
#define OFF_ZQ   8388608
#define OFF_IDX  16777216
#define OFF_ST   16809984

#define CAP   64
#define DELTA 0.30f     // > 2x worst-case bf16 screening error (0.13)

// ---------------- device scratch (static; no allocations) -------------------
__device__ float g_en2[KCODE];
__device__ int   g_usage[KCODE];
__device__ int   g_cnt[NROWS];
__device__ int   g_cand[NROWS * CAP];
__device__ float g_entsum;
__device__ int   g_deadsum;
__device__ __align__(16) __nv_bfloat16 g_Abf[NROWS * DIM];
__device__ __align__(16) __nv_bfloat16 g_Ebf[KCODE * DIM];

// ---------------- helpers ----------------------------------------------------
__device__ __forceinline__ uint32_t smem_u32(const void* p) {
    uint32_t a;
    asm("{ .reg .u64 t; cvta.to.shared.u64 t, %1; cvt.u32.u64 %0, t; }" : "=r"(a) : "l"(p));
    return a;
}
#define CP_ASYNC(dst, src) \
    asm volatile("cp.async.cg.shared.global [%0], [%1], 16;" :: "r"(dst), "l"(src) : "memory")
#define CP_COMMIT() asm volatile("cp.async.commit_group;" ::: "memory")
#define CP_WAIT1()  asm volatile("cp.async.wait_group 1;" ::: "memory")

#define LDSM_X4(r0, r1, r2, r3, addr) \
    asm volatile("ldmatrix.sync.aligned.m8n8.x4.shared.b16 {%0,%1,%2,%3}, [%4];" \
                 : "=r"(r0), "=r"(r1), "=r"(r2), "=r"(r3) : "r"(addr))

__device__ __forceinline__ void mma16816(float* d, const uint32_t* a, uint32_t b0, uint32_t b1) {
    asm volatile(
        "mma.sync.aligned.m16n8k16.row.col.f32.bf16.bf16.f32 "
        "{%0,%1,%2,%3}, {%4,%5,%6,%7}, {%8,%9}, {%0,%1,%2,%3};"
        : "+f"(d[0]), "+f"(d[1]), "+f"(d[2]), "+f"(d[3])
        : "r"(a[0]), "r"(a[1]), "r"(a[2]), "r"(a[3]), "r"(b0), "r"(b1));
}

// Monotonic float<->uint key (min over uints == min over floats).
__device__ __forceinline__ uint32_t fkey(float f) {
    uint32_t b = __float_as_uint(f);
    return (b & 0x80000000u) ? ~b : (b | 0x80000000u);
}
__device__ __forceinline__ float funkey(uint32_t k) {
    uint32_t b = (k & 0x80000000u) ? (k ^ 0x80000000u) : ~k;
    return __uint_as_float(b);
}
#define KEY_INF 0xFF800000u   // fkey(+inf)

// Swizzled byte offset inside a [rows x 256 bf16] tile: row r, 16B-chunk c (0..31).
__device__ __forceinline__ uint32_t TOFF(int r, int c) {
    return ((uint32_t)r << 9) + ((uint32_t)(c ^ (r & 7)) << 4);
}

// ---------------- prep kernels ----------------------------------------------
__global__ void prep_a(const float* __restrict__ Z) {
    int i = blockIdx.x * blockDim.x + threadIdx.x;
    float4 v = reinterpret_cast<const float4*>(Z)[i];
    __nv_bfloat162 p0(__float2bfloat16(v.x), __float2bfloat16(v.y));
    __nv_bfloat162 p1(__float2bfloat16(v.z), __float2bfloat16(v.w));
    reinterpret_cast<__nv_bfloat162*>(g_Abf)[2 * i + 0] = p0;
    reinterpret_cast<__nv_bfloat162*>(g_Abf)[2 * i + 1] = p1;
}
__global__ void prep_econv(const float* __restrict__ E) {
    int i = blockIdx.x * blockDim.x + threadIdx.x;
    float4 v = reinterpret_cast<const float4*>(E)[i];
    __nv_bfloat162 p0(__float2bfloat16(v.x), __float2bfloat16(v.y));
    __nv_bfloat162 p1(__float2bfloat16(v.z), __float2bfloat16(v.w));
    reinterpret_cast<__nv_bfloat162*>(g_Ebf)[2 * i + 0] = p0;
    reinterpret_cast<__nv_bfloat162*>(g_Ebf)[2 * i + 1] = p1;
}
__global__ void prep_en2(const float* __restrict__ E) {
    int j = blockIdx.x * blockDim.x + threadIdx.x;
    if (j == 0) { g_entsum = 0.0f; g_deadsum = 0; }
    if (j >= KCODE) return;
    g_usage[j] = 0;
    const float4* p = reinterpret_cast<const float4*>(E + (size_t)j * DIM);
    float s = 0.0f;
#pragma unroll
    for (int i = 0; i < DIM / 4; i++) {
        float4 v = p[i];
        s = fmaf(v.x, v.x, s); s = fmaf(v.y, v.y, s);
        s = fmaf(v.z, v.z, s); s = fmaf(v.w, v.w, s);
    }
    g_en2[j] = s;
}

// ---------------- screening GEMM (mma.sync bf16) -----------------------------
// CTA: 128 rows (A resident, 64KB swizzled), 512 threads, warp grid 4m x 4n,
// warp tile 32x32. 64 chunks of 128 codes, double-buffered via cp.async.
// Lock-free per-row best via smem atomicMin on monotonic float keys;
// candidate scan reads the (stale-tolerant) key -> 2 barriers per chunk.
#define NCH   64
#define SM_A      0
#define SM_B0     65536           // two 64KB buffers
#define SM_ESM    196608          // 2 x 128 floats
#define SM_BKEY   197632          // 128 uint keys
#define SM_CNT    198144          // 128 ints
#define SM_TOTAL  198656

__global__ __launch_bounds__(512, 1) void vq_screen() {
    extern __shared__ __align__(1024) char smem[];
    const uint32_t sb = smem_u32(smem);
    const int tid = threadIdx.x, lane = tid & 31, wid = tid >> 5;
    const int wm = wid & 3, wn = wid >> 2;
    const int row0 = blockIdx.x * 128;

    uint32_t* bkey = reinterpret_cast<uint32_t*>(smem + SM_BKEY);
    int*      scnt = reinterpret_cast<int*>(smem + SM_CNT);
    if (tid < 128) { bkey[tid] = KEY_INF; scnt[tid] = 0; }

    // Prologue: group0 = A + B0 + esm0 ; group1 = B1 + esm1
#pragma unroll
    for (int t = 0; t < 8; t++) {
        int u = tid + t * 512, r = u >> 5, c = u & 31;
        CP_ASYNC(sb + SM_A + TOFF(r, c), g_Abf + (size_t)(row0 + r) * DIM + c * 8);
    }
#pragma unroll
    for (int t = 0; t < 8; t++) {
        int u = tid + t * 512, r = u >> 5, c = u & 31;
        CP_ASYNC(sb + SM_B0 + TOFF(r, c), g_Ebf + (size_t)r * DIM + c * 8);
    }
    if (tid < 32) CP_ASYNC(sb + SM_ESM + tid * 16, g_en2 + tid * 4);
    CP_COMMIT();
#pragma unroll
    for (int t = 0; t < 8; t++) {
        int u = tid + t * 512, r = u >> 5, c = u & 31;
        CP_ASYNC(sb + SM_B0 + 65536 + TOFF(r, c), g_Ebf + (size_t)(128 + r) * DIM + c * 8);
    }
    if (tid < 32) CP_ASYNC(sb + SM_ESM + 512 + tid * 16, g_en2 + 128 + tid * 4);
    CP_COMMIT();
    CP_WAIT1();
    __syncthreads();

    const int s7 = lane & 7;
    const int cxA = lane >> 4;
    const int cxB = (lane >> 3) & 1;
    uint32_t rowA[2], rowB[2];
#pragma unroll
    for (int i = 0; i < 2; i++)
        rowA[i] = sb + SM_A + ((uint32_t)(wm * 32 + i * 16 + ((lane >> 3) & 1) * 8 + s7) << 9);
#pragma unroll
    for (int jj = 0; jj < 2; jj++)
        rowB[jj] = (uint32_t)(wn * 32 + jj * 16 + ((lane >> 4) & 1) * 8 + s7) << 9;

    float acc[2][4][4];
#pragma unroll
    for (int i = 0; i < 2; i++)
#pragma unroll
        for (int j = 0; j < 4; j++)
#pragma unroll
            for (int r = 0; r < 4; r++) acc[i][j][r] = 0.0f;

    for (int ch = 0; ch < NCH; ch++) {
        const int buf = ch & 1;
        const uint32_t bbase = sb + SM_B0 + (uint32_t)buf * 65536;

        // ---- compute: 16 k-steps ----
#pragma unroll
        for (int ks = 0; ks < 16; ks++) {
            const uint32_t offA = (uint32_t)(((2 * ks + cxA) ^ s7) << 4);
            const uint32_t offB = (uint32_t)(((2 * ks + cxB) ^ s7) << 4);
            uint32_t a[2][4], b[2][4];
#pragma unroll
            for (int i = 0; i < 2; i++)
                LDSM_X4(a[i][0], a[i][1], a[i][2], a[i][3], rowA[i] + offA);
#pragma unroll
            for (int jj = 0; jj < 2; jj++)
                LDSM_X4(b[jj][0], b[jj][1], b[jj][2], b[jj][3], bbase + rowB[jj] + offB);
#pragma unroll
            for (int i = 0; i < 2; i++) {
                mma16816(acc[i][0], a[i], b[0][0], b[0][1]);
                mma16816(acc[i][1], a[i], b[0][2], b[0][3]);
                mma16816(acc[i][2], a[i], b[1][0], b[1][1]);
                mma16816(acc[i][3], a[i], b[1][2], b[1][3]);
            }
        }
        __syncthreads();     // all warps done reading Bs[buf]

        // prefetch chunk ch+2 into buf (overlaps epilogue + next compute)
        if (ch + 2 < NCH) {
            const __nv_bfloat16* src = g_Ebf + (size_t)(ch + 2) * 128 * DIM;
#pragma unroll
            for (int t = 0; t < 8; t++) {
                int u = tid + t * 512, r = u >> 5, c = u & 31;
                CP_ASYNC(bbase + TOFF(r, c), src + (size_t)r * DIM + c * 8);
            }
            if (tid < 32)
                CP_ASYNC(sb + SM_ESM + buf * 512 + tid * 16, g_en2 + (ch + 2) * 128 + tid * 4);
        }
        CP_COMMIT();

        // ---- epilogue: distances, lock-free row best, candidate scan ----
        const float* esm = reinterpret_cast<const float*>(smem + SM_ESM + buf * 512);
        float rmin[2][2];
#pragma unroll
        for (int i = 0; i < 2; i++) {
            rmin[i][0] = 3.4e38f; rmin[i][1] = 3.4e38f;
#pragma unroll
            for (int j = 0; j < 4; j++) {
                const int colb = wn * 32 + j * 8 + (lane & 3) * 2;
                const float e0 = esm[colb], e1 = esm[colb + 1];
                float d0 = fmaf(-2.0f, acc[i][j][0], e0);
                float d1 = fmaf(-2.0f, acc[i][j][1], e1);
                float d2 = fmaf(-2.0f, acc[i][j][2], e0);
                float d3 = fmaf(-2.0f, acc[i][j][3], e1);
                acc[i][j][0] = d0; acc[i][j][1] = d1;
                acc[i][j][2] = d2; acc[i][j][3] = d3;
                rmin[i][0] = fminf(rmin[i][0], fminf(d0, d1));
                rmin[i][1] = fminf(rmin[i][1], fminf(d2, d3));
            }
            rmin[i][0] = fminf(rmin[i][0], __shfl_xor_sync(0xffffffffu, rmin[i][0], 1));
            rmin[i][0] = fminf(rmin[i][0], __shfl_xor_sync(0xffffffffu, rmin[i][0], 2));
            rmin[i][1] = fminf(rmin[i][1], __shfl_xor_sync(0xffffffffu, rmin[i][1], 1));
            rmin[i][1] = fminf(rmin[i][1], __shfl_xor_sync(0xffffffffu, rmin[i][1], 2));
        }
        if ((lane & 3) == 0) {
#pragma unroll
            for (int i = 0; i < 2; i++) {
                const int r = wm * 32 + i * 16 + (lane >> 2);
                atomicMin(&bkey[r], fkey(rmin[i][0]));
                atomicMin(&bkey[r + 8], fkey(rmin[i][1]));
            }
        }

        // candidate scan vs (stale-tolerant) shared best — looser threshold is
        // always a superset; rescore tie-breaks by index explicitly.
#pragma unroll
        for (int i = 0; i < 2; i++) {
            const int rA = wm * 32 + i * 16 + (lane >> 2);
            const int rB = rA + 8;
            const float lA = funkey(bkey[rA]) + DELTA;
            const float lB = funkey(bkey[rB]) + DELTA;
#pragma unroll
            for (int j = 0; j < 4; j++) {
                const int code = ch * 128 + wn * 32 + j * 8 + (lane & 3) * 2;
                if (acc[i][j][0] < lA) {
                    int s = atomicAdd(&scnt[rA], 1);
                    if (s < CAP) g_cand[(size_t)(row0 + rA) * CAP + s] = code;
                }
                if (acc[i][j][1] < lA) {
                    int s = atomicAdd(&scnt[rA], 1);
                    if (s < CAP) g_cand[(size_t)(row0 + rA) * CAP + s] = code + 1;
                }
                if (acc[i][j][2] < lB) {
                    int s = atomicAdd(&scnt[rB], 1);
                    if (s < CAP) g_cand[(size_t)(row0 + rB) * CAP + s] = code;
                }
                if (acc[i][j][3] < lB) {
                    int s = atomicAdd(&scnt[rB], 1);
                    if (s < CAP) g_cand[(size_t)(row0 + rB) * CAP + s] = code + 1;
                }
                acc[i][j][0] = 0.0f; acc[i][j][1] = 0.0f;
                acc[i][j][2] = 0.0f; acc[i][j][3] = 0.0f;
            }
        }
        CP_WAIT1();          // chunk ch+1 resident
        __syncthreads();
    }

    if (tid < 128) g_cnt[row0 + tid] = scnt[tid];
}

// ---------------- exact rescore + gather (fused) ------------------------------
__global__ void rescore_gather(const float* __restrict__ Z,
                               const float* __restrict__ E,
                               float* __restrict__ out) {
    const int row = (blockIdx.x * blockDim.x + threadIdx.x) >> 5;
    const int lane = threadIdx.x & 31;
    if (row >= NROWS) return;
    const float4* zp = reinterpret_cast<const float4*>(Z + (size_t)row * DIM);
    const float4 a0 = zp[lane * 2], a1 = zp[lane * 2 + 1];
    const int cnt = g_cnt[row];
    const bool full = cnt > CAP;
    const int n = full ? KCODE : cnt;
    float bd = 3.4e38f; int bi = 0;
    for (int k = 0; k < n; k++) {
        const int code = full ? k : g_cand[(size_t)row * CAP + k];
        const float4* e = reinterpret_cast<const float4*>(E + (size_t)code * DIM);
        const float4 e0 = e[lane * 2], e1 = e[lane * 2 + 1];
        float s = a0.x * e0.x;
        s = fmaf(a0.y, e0.y, s); s = fmaf(a0.z, e0.z, s); s = fmaf(a0.w, e0.w, s);
        s = fmaf(a1.x, e1.x, s); s = fmaf(a1.y, e1.y, s);
        s = fmaf(a1.z, e1.z, s); s = fmaf(a1.w, e1.w, s);
#pragma unroll
        for (int o = 16; o; o >>= 1) s += __shfl_xor_sync(0xffffffffu, s, o);
        float d = fmaf(-2.0f, s, g_en2[code]);
        if (d < bd || (d == bd && code < bi)) { bd = d; bi = code; }
    }
    // every lane agrees on bi; gather + write outputs
    const float4* e = reinterpret_cast<const float4*>(E + (size_t)bi * DIM);
    const float4 e0 = e[lane * 2], e1 = e[lane * 2 + 1];
    const size_t o = (size_t)row * DIM + lane * 8;
    float4 st0, st1;
    st0.x = a0.x + (e0.x - a0.x); st0.y = a0.y + (e0.y - a0.y);
    st0.z = a0.z + (e0.z - a0.z); st0.w = a0.w + (e0.w - a0.w);
    st1.x = a1.x + (e1.x - a1.x); st1.y = a1.y + (e1.y - a1.y);
    st1.z = a1.z + (e1.z - a1.z); st1.w = a1.w + (e1.w - a1.w);
    reinterpret_cast<float4*>(out + o)[0] = st0;
    reinterpret_cast<float4*>(out + o)[1] = st1;
    reinterpret_cast<float4*>(out + OFF_ZQ + o)[0] = e0;
    reinterpret_cast<float4*>(out + OFF_ZQ + o)[1] = e1;
    if (lane == 0) {
        out[OFF_IDX + row] = (float)bi;
        atomicAdd(&g_usage[bi], 1);
    }
}

// ---------------- stats: parallel partial + tiny finalize --------------------
__global__ void stats_part() {
    __shared__ float se[256];
    __shared__ int   sd[256];
    int j = blockIdx.x * 256 + threadIdx.x;
    int u = g_usage[j];
    float ent = 0.0f; int dead = 0;
    if (u == 0) dead = 1;
    else { float p = (float)u * (1.0f / (float)NROWS); ent = -p * logf(p); }
    se[threadIdx.x] = ent; sd[threadIdx.x] = dead;
    __syncthreads();
    for (int s = 128; s > 0; s >>= 1) {
        if (threadIdx.x < s) { se[threadIdx.x] += se[threadIdx.x + s]; sd[threadIdx.x] += sd[threadIdx.x + s]; }
        __syncthreads();
    }
    if (threadIdx.x == 0) {
        atomicAdd(&g_entsum, se[0]);
        atomicAdd(&g_deadsum, sd[0]);
    }
}
__global__ void stats_fin(float* __restrict__ out) {
    out[OFF_ST + 0] = expf(g_entsum);
    out[OFF_ST + 1] = (float)g_deadsum / (float)KCODE;
}

// ---------------------------------------------------------------------------
extern "C" void kernel_launch(void* const* d_in, const int* in_sizes, int n_in,
                              void* d_out, int out_size) {
    const float* z_e = (const float*)d_in[0];
    const float* emb = (const float*)d_in[1];
    float* out = (float*)d_out;

    cudaFuncSetAttribute(vq_screen, cudaFuncAttributeMaxDynamicSharedMemorySize, SM_TOTAL);

    prep_a<<<NZ / 1024, 256>>>(z_e);
    prep_econv<<<(KCODE * DIM) / 1024, 256>>>(emb);
    prep_en2<<<KCODE / 256, 256>>>(emb);
    vq_screen<<<NROWS / 128, 512, SM_TOTAL>>>();
    rescore_gather<<<NROWS / 8, 256>>>(z_e, emb, out);
    stats_part<<<KCODE / 256, 256>>>();
    stats_fin<<<1, 1>>>(out);
}